// round 2
// baseline (speedup 1.0000x reference)
#include <cuda_runtime.h>

#define NN   100000
#define NE   3200000
#define FIN  1024
#define HID  16
#define NCLS 40

// ---------------- device scratch (no allocations allowed) ----------------
__device__ int    g_deg[NN];
__device__ float  g_invdeg[NN];
__device__ int    g_rowptr[NN + 1];
__device__ int    g_cursor[NN];
__device__ int    g_es[NE];
__device__ float  g_ep[NE];
__device__ float  g_C1[NN * 48];        // per-node [y0(16) | y1(16) | x@root1(16)]
__device__ float  g_W1cat[FIN * 48];    // [W1_0 | W1_1 | root1] col-concat, row stride 48
__device__ float  g_W2cat[48 * NCLS];   // rows: W2_0(16), W2_1(16), root2(16)
__device__ __align__(16) float g_AB[NN * 32];   // per-node [A(16) | B(16)]  (scaled by 1/deg)
__device__ __align__(16) float g_x1[NN * HID];  // hidden activations

__device__ __forceinline__ int clampN(int v) {
    v = v < 0 ? 0 : v;
    return v >= NN ? NN - 1 : v;
}

// ---------------- CSR build ----------------
__global__ void k_zero_deg() {
    int i = blockIdx.x * blockDim.x + threadIdx.x;
    if (i < NN) g_deg[i] = 0;
}

__global__ void k_degree(const int* __restrict__ ei) {
    int e = blockIdx.x * blockDim.x + threadIdx.x;
    if (e < NE) atomicAdd(&g_deg[clampN(ei[NE + e])], 1);
}

__global__ void k_scan() {
    __shared__ int ss[1024];
    int tid = threadIdx.x;
    const int per = (NN + 1023) / 1024;   // 98
    int start = tid * per;
    int end = start + per; if (end > NN) end = NN;
    if (start > NN) start = NN;
    int s = 0;
    for (int i = start; i < end; i++) s += g_deg[i];
    ss[tid] = s;
    __syncthreads();
    for (int off = 1; off < 1024; off <<= 1) {
        int add = (tid >= off) ? ss[tid - off] : 0;
        __syncthreads();
        ss[tid] += add;
        __syncthreads();
    }
    int run = (tid > 0) ? ss[tid - 1] : 0;
    for (int i = start; i < end; i++) {
        int d = g_deg[i];
        g_rowptr[i] = run;
        g_cursor[i] = run;
        g_invdeg[i] = 1.0f / (float)(d > 0 ? d : 1);
        run += d;
    }
    if (tid == 1023) g_rowptr[NN] = run;
}

__global__ void k_scatter(const int* __restrict__ ei, const float* __restrict__ pa) {
    int e = blockIdx.x * blockDim.x + threadIdx.x;
    if (e >= NE) return;
    int s = clampN(ei[e]);
    int d = clampN(ei[NE + e]);
    int pos = atomicAdd(&g_cursor[d], 1);
    if (pos >= 0 && pos < NE) {
        g_es[pos] = s;
        g_ep[pos] = pa[e];
    }
}

// ---------------- weight packing ----------------
__global__ void k_pack1(const float* __restrict__ W1, const float* __restrict__ root1) {
    int idx = blockIdx.x * blockDim.x + threadIdx.x;
    if (idx >= FIN * 48) return;
    int k = idx / 48, j = idx % 48;
    float v;
    if (j < 16)      v = W1[k * 16 + j];
    else if (j < 32) v = W1[FIN * 16 + k * 16 + (j - 16)];
    else             v = root1[k * 16 + (j - 32)];
    g_W1cat[idx] = v;
}

__global__ void k_pack2(const float* __restrict__ W2, const float* __restrict__ root2) {
    int idx = blockIdx.x * blockDim.x + threadIdx.x;
    if (idx >= 48 * NCLS) return;
    int r = idx / NCLS, c = idx % NCLS;
    float v;
    if (r < 16)      v = W2[r * NCLS + c];
    else if (r < 32) v = W2[16 * NCLS + (r - 16) * NCLS + c];
    else             v = root2[(r - 32) * NCLS + c];
    g_W2cat[idx] = v;
}

// ---------------- GEMM1: C1 = x @ W1cat  (100000x1024 @ 1024x48) ----------------
// BM=128, BN=48, BK=32. 128 threads, thread tile 8x6.
__global__ __launch_bounds__(128) void k_gemm1(const float* __restrict__ x) {
    __shared__ __align__(16) float As[32][132];   // [k][m], padded
    __shared__ __align__(16) float Bs[32][48];    // [k][n]
    int t = threadIdx.x;
    int mBase = blockIdx.x * 128;
    int ty8 = (t >> 3) * 8;     // row offset (0..120)
    int tx6 = (t & 7) * 6;      // col offset (0..42)
    float acc[8][6];
#pragma unroll
    for (int i = 0; i < 8; i++)
#pragma unroll
        for (int j = 0; j < 6; j++) acc[i][j] = 0.f;

    for (int k0 = 0; k0 < FIN; k0 += 32) {
        // load x tile: 128x32 floats = 1024 float4, 8 per thread
#pragma unroll
        for (int i = 0; i < 8; i++) {
            int q = t + i * 128;
            int r = q >> 3;
            int kq = (q & 7) << 2;
            int gr = mBase + r;
            float4 v = make_float4(0.f, 0.f, 0.f, 0.f);
            if (gr < NN) v = *(const float4*)(x + (long)gr * FIN + k0 + kq);
            As[kq + 0][r] = v.x;
            As[kq + 1][r] = v.y;
            As[kq + 2][r] = v.z;
            As[kq + 3][r] = v.w;
        }
        // load W tile: 32x48 floats = 1536, 12 per thread (scalar stores)
#pragma unroll
        for (int i = 0; i < 12; i++) {
            int q = t + i * 128;
            int kk = q / 48;
            int jq = q % 48;
            Bs[kk][jq] = g_W1cat[(k0 + kk) * 48 + jq];
        }
        __syncthreads();
#pragma unroll
        for (int kk = 0; kk < 32; kk++) {
            float a[8], b[6];
#pragma unroll
            for (int i = 0; i < 8; i++) a[i] = As[kk][ty8 + i];
#pragma unroll
            for (int j = 0; j < 6; j++) b[j] = Bs[kk][tx6 + j];
#pragma unroll
            for (int i = 0; i < 8; i++)
#pragma unroll
                for (int j = 0; j < 6; j++) acc[i][j] = fmaf(a[i], b[j], acc[i][j]);
        }
        __syncthreads();
    }
#pragma unroll
    for (int i = 0; i < 8; i++) {
        int row = mBase + ty8 + i;
        if (row < NN) {
#pragma unroll
            for (int j = 0; j < 6; j++) g_C1[row * 48 + tx6 + j] = acc[i][j];
        }
    }
}

// ---------------- layer-1 aggregation + ELU (warp per node) ----------------
__global__ void k_agg1(const float* __restrict__ b1, float* __restrict__ x1out, int writeOut) {
    int w = (blockIdx.x * blockDim.x + threadIdx.x) >> 5;
    if (w >= NN) return;
    int lane = threadIdx.x & 31;
    int c = lane & 15;
    int h = lane >> 4;
    int start = g_rowptr[w];
    int deg = g_deg[w];
    float acc = 0.f;
    for (int e = start + h; e < start + deg; e += 2) {
        int s = g_es[e];
        float p = g_ep[e];
        float y0 = g_C1[s * 48 + c];
        float y1 = g_C1[s * 48 + 16 + c];
        acc += fmaf(p, y1 - y0, y0);
    }
    acc += __shfl_down_sync(0xffffffffu, acc, 16);
    if (h == 0) {
        float v = fmaf(acc, g_invdeg[w], g_C1[w * 48 + 32 + c] + b1[c]);
        v = (v > 0.f) ? v : expm1f(v);
        g_x1[w * 16 + c] = v;
        if (writeOut) x1out[w * 16 + c] = v;
    }
}

// ---------------- layer-2 aggregation in input space (warp per node) ----------------
// A[dst] = sum (1-p) x1[src], B[dst] = sum p x1[src]   (both /deg)
__global__ void k_agg2() {
    int w = (blockIdx.x * blockDim.x + threadIdx.x) >> 5;
    if (w >= NN) return;
    int lane = threadIdx.x & 31;
    int c = lane & 15;
    int h = lane >> 4;
    int start = g_rowptr[w];
    int deg = g_deg[w];
    float accS = 0.f;   // sum x1
    float accB = 0.f;   // sum p*x1
    for (int e = start + h; e < start + deg; e += 2) {
        int s = g_es[e];
        float p = g_ep[e];
        float xv = g_x1[s * 16 + c];
        accS += xv;
        accB = fmaf(p, xv, accB);
    }
    accS += __shfl_down_sync(0xffffffffu, accS, 16);
    accB += __shfl_down_sync(0xffffffffu, accB, 16);
    if (h == 0) {
        float inv = g_invdeg[w];
        g_AB[w * 32 + c]      = (accS - accB) * inv;   // A = S - B
        g_AB[w * 32 + 16 + c] = accB * inv;
    }
}

// ---------------- GEMM2 + bias + log_softmax (thread per node) ----------------
__global__ __launch_bounds__(256) void k_out(const float* __restrict__ b2,
                                             float* __restrict__ out) {
    __shared__ float Ws[48 * NCLS];
    for (int i = threadIdx.x; i < 48 * NCLS; i += 256) Ws[i] = g_W2cat[i];
    __syncthreads();
    int node = blockIdx.x * 256 + threadIdx.x;
    if (node >= NN) return;

    float acc[NCLS];
#pragma unroll
    for (int cx = 0; cx < NCLS; cx++) acc[cx] = b2[cx];

    const float* ab = g_AB + node * 32;
#pragma unroll 4
    for (int r = 0; r < 32; r++) {
        float vv = ab[r];
        const float* wr = &Ws[r * NCLS];
#pragma unroll
        for (int cx = 0; cx < NCLS; cx++) acc[cx] = fmaf(vv, wr[cx], acc[cx]);
    }
    const float* xx = g_x1 + node * 16;
#pragma unroll 4
    for (int r = 0; r < 16; r++) {
        float vv = xx[r];
        const float* wr = &Ws[(32 + r) * NCLS];
#pragma unroll
        for (int cx = 0; cx < NCLS; cx++) acc[cx] = fmaf(vv, wr[cx], acc[cx]);
    }

    float m = acc[0];
#pragma unroll
    for (int cx = 1; cx < NCLS; cx++) m = fmaxf(m, acc[cx]);
    float ssum = 0.f;
#pragma unroll
    for (int cx = 0; cx < NCLS; cx++) ssum += expf(acc[cx] - m);
    float l = m + logf(ssum);
#pragma unroll
    for (int cx = 0; cx < NCLS; cx++) out[node * NCLS + cx] = acc[cx] - l;
}

// ---------------- launch ----------------
extern "C" void kernel_launch(void* const* d_in, const int* in_sizes, int n_in,
                              void* d_out, int out_size) {
    const float* x     = (const float*)d_in[0];
    const int*   ei    = (const int*)d_in[1];     // int32! (jax x64 disabled)
    const float* pa    = (const float*)d_in[2];
    const float* W1    = (const float*)d_in[3];
    const float* root1 = (const float*)d_in[4];
    const float* b1    = (const float*)d_in[5];
    const float* W2    = (const float*)d_in[6];
    const float* root2 = (const float*)d_in[7];
    const float* b2    = (const float*)d_in[8];
    float* out = (float*)d_out;

    // x1 slot in the output (tuple: logp[NN*NCLS] then x1[NN*HID]); guard by out_size
    int writeOut = (out_size >= NN * (NCLS + HID)) ? 1 : 0;
    float* x1out = out + (long)NN * NCLS;

    k_zero_deg<<<(NN + 255) / 256, 256>>>();
    k_degree<<<NE / 256, 256>>>(ei);
    k_scan<<<1, 1024>>>();
    k_scatter<<<NE / 256, 256>>>(ei, pa);
    k_pack1<<<(FIN * 48 + 255) / 256, 256>>>(W1, root1);
    k_pack2<<<(48 * NCLS + 255) / 256, 256>>>(W2, root2);
    k_gemm1<<<(NN + 127) / 128, 128>>>(x);
    k_agg1<<<NN / 8, 256>>>(b1, x1out, writeOut);
    k_agg2<<<NN / 8, 256>>>();
    k_out<<<(NN + 255) / 256, 256>>>(b2, out);
}

// round 5
// speedup vs baseline: 1.1354x; 1.1354x over previous
#include <cuda_runtime.h>
#include <cuda_bf16.h>
#include <cstdint>

#define NN   100000
#define NE   3200000
#define FIN  1024
#define HID  16
#define NCLS 40

// ---------------- device scratch ----------------
__device__ int    g_deg[NN];
__device__ float  g_invdeg[NN];
__device__ int    g_rowptr[NN + 1];
__device__ int    g_cursor[NN];
__device__ __align__(16) int2  g_esp[NE];          // (src, p-bits) per CSR slot
__device__ __align__(16) float g_Y[NN * 32];       // per-node interleaved [y0_c, y1_c] x16
__device__ __align__(16) float g_R[NN * 16];       // x@root1
__device__ __align__(16) __nv_bfloat16 g_Wbhi[48 * FIN];  // [n][k] hi split
__device__ __align__(16) __nv_bfloat16 g_Wblo[48 * FIN];  // [n][k] lo split
__device__ float  g_W2cat[48 * NCLS];
__device__ __align__(16) float g_AB[NN * 32];
__device__ __align__(16) float g_x1[NN * HID];

__device__ __forceinline__ int clampN(int v) {
    v = v < 0 ? 0 : v;
    return v >= NN ? NN - 1 : v;
}

// ---------------- CSR build ----------------
__global__ void k_zero_deg() {
    int i = blockIdx.x * blockDim.x + threadIdx.x;
    if (i < NN) g_deg[i] = 0;
}

__global__ void k_degree(const int* __restrict__ ei) {
    int e = blockIdx.x * blockDim.x + threadIdx.x;
    if (e < NE) atomicAdd(&g_deg[clampN(ei[NE + e])], 1);
}

__global__ void k_scan() {
    __shared__ int ss[1024];
    int tid = threadIdx.x;
    const int per = (NN + 1023) / 1024;
    int start = tid * per;
    int end = start + per; if (end > NN) end = NN;
    if (start > NN) start = NN;
    int s = 0;
    for (int i = start; i < end; i++) s += g_deg[i];
    ss[tid] = s;
    __syncthreads();
    for (int off = 1; off < 1024; off <<= 1) {
        int add = (tid >= off) ? ss[tid - off] : 0;
        __syncthreads();
        ss[tid] += add;
        __syncthreads();
    }
    int run = (tid > 0) ? ss[tid - 1] : 0;
    for (int i = start; i < end; i++) {
        int d = g_deg[i];
        g_rowptr[i] = run;
        g_cursor[i] = run;
        g_invdeg[i] = 1.0f / (float)(d > 0 ? d : 1);
        run += d;
    }
    if (tid == 1023) g_rowptr[NN] = run;
}

__global__ void k_scatter(const int* __restrict__ ei, const float* __restrict__ pa) {
    int e = blockIdx.x * blockDim.x + threadIdx.x;
    if (e >= NE) return;
    int s = clampN(ei[e]);
    int d = clampN(ei[NE + e]);
    int pos = atomicAdd(&g_cursor[d], 1);
    if (pos >= 0 && pos < NE) {
        g_esp[pos] = make_int2(s, __float_as_int(pa[e]));
    }
}

// ---------------- weight packing (bf16 hi/lo split, [n][k]) ----------------
__global__ void k_packW(const float* __restrict__ W1, const float* __restrict__ root1) {
    int idx = blockIdx.x * blockDim.x + threadIdx.x;
    if (idx >= 48 * FIN) return;
    int n = idx >> 10, k = idx & 1023;
    float v;
    if (n < 16)      v = W1[k * 16 + n];
    else if (n < 32) v = W1[FIN * 16 + k * 16 + (n - 16)];
    else             v = root1[k * 16 + (n - 32)];
    __nv_bfloat16 h = __float2bfloat16(v);
    __nv_bfloat16 l = __float2bfloat16(v - __bfloat162float(h));
    g_Wbhi[idx] = h;
    g_Wblo[idx] = l;
}

__global__ void k_pack2(const float* __restrict__ W2, const float* __restrict__ root2) {
    int idx = blockIdx.x * blockDim.x + threadIdx.x;
    if (idx >= 48 * NCLS) return;
    int r = idx / NCLS, c = idx % NCLS;
    float v;
    if (r < 16)      v = W2[r * NCLS + c];
    else if (r < 32) v = W2[16 * NCLS + (r - 16) * NCLS + c];
    else             v = root2[(r - 32) * NCLS + c];
    g_W2cat[idx] = v;
}

// ---------------- GEMM1 via mma.sync bf16 (double split) ----------------
// C[100000 x 48] = x[100000 x 1024] @ W[1024 x 48]
// CTA: 256 thr / 8 warps. M=128 (16 rows per warp), N=48 (6 n8 tiles), K-chunk 64.
#define AST 72   // A smem row stride in bf16 elems (conflict-free)
#define BST 72
#define SM_AH 0
#define SM_AL (128 * AST * 2)                 // 18432
#define SM_BH (2 * 128 * AST * 2)             // 36864
#define SM_BL (2 * 128 * AST * 2 + 48 * BST * 2)  // 43776
#define G1_SMEM (2 * 128 * AST * 2 + 2 * 48 * BST * 2)  // 50688

#define MMA_BF16(d, a, b) \
    asm volatile("mma.sync.aligned.m16n8k16.row.col.f32.bf16.bf16.f32 " \
        "{%0,%1,%2,%3}, {%4,%5,%6,%7}, {%8,%9}, {%0,%1,%2,%3};" \
        : "+f"((d)[0]), "+f"((d)[1]), "+f"((d)[2]), "+f"((d)[3]) \
        : "r"((a)[0]), "r"((a)[1]), "r"((a)[2]), "r"((a)[3]), "r"((b)[0]), "r"((b)[1]))

__device__ __forceinline__ uint32_t split_hi(float a, float b, uint32_t& lo) {
    __nv_bfloat162 h = __floats2bfloat162_rn(a, b);
    float ra = a - __low2float(h);
    float rb = b - __high2float(h);
    __nv_bfloat162 L = __floats2bfloat162_rn(ra, rb);
    lo = *(uint32_t*)&L;
    return *(uint32_t*)&h;
}

__device__ __forceinline__ void storeC(long row, int j, float v) {
    if (row >= NN) return;
    if (j < 16)      g_Y[row * 32 + 2 * j] = v;
    else if (j < 32) g_Y[row * 32 + 2 * (j - 16) + 1] = v;
    else             g_R[row * 16 + (j - 32)] = v;
}

__global__ __launch_bounds__(256) void k_gemm1_mma(const float* __restrict__ x) {
    extern __shared__ __align__(16) char sm[];
    __nv_bfloat16* Ah = (__nv_bfloat16*)(sm + SM_AH);
    __nv_bfloat16* Al = (__nv_bfloat16*)(sm + SM_AL);
    __nv_bfloat16* Bh = (__nv_bfloat16*)(sm + SM_BH);
    __nv_bfloat16* Bl = (__nv_bfloat16*)(sm + SM_BL);
    int tid = threadIdx.x, w = tid >> 5, l = tid & 31;
    int lq = l >> 2, lr = l & 3;
    long mBase = (long)blockIdx.x * 128;

    float acc[6][4];
#pragma unroll
    for (int t = 0; t < 6; t++)
#pragma unroll
        for (int i = 0; i < 4; i++) acc[t][i] = 0.f;

    for (int kb = 0; kb < 16; kb++) {
        int k0 = kb * 64;
        // ---- fill A (128 x 64 fp32 -> bf16 hi/lo) ----
#pragma unroll
        for (int i = 0; i < 8; i++) {
            int idx = tid + i * 256;
            int r = idx >> 4, c4 = (idx & 15) * 4;
            float4 v = make_float4(0.f, 0.f, 0.f, 0.f);
            long gr = mBase + r;
            if (gr < NN) v = *(const float4*)(x + gr * FIN + k0 + c4);
            uint32_t l0, l1;
            uint32_t h0 = split_hi(v.x, v.y, l0);
            uint32_t h1 = split_hi(v.z, v.w, l1);
            *(uint2*)(Ah + r * AST + c4) = make_uint2(h0, h1);
            *(uint2*)(Al + r * AST + c4) = make_uint2(l0, l1);
        }
        // ---- fill B (48 x 64 bf16 hi/lo) ----
        for (int i = tid; i < 384; i += 256) {
            int n = i >> 3, c8 = (i & 7) * 8;
            uint4 vh = *(const uint4*)(g_Wbhi + n * FIN + k0 + c8);
            uint4 vl = *(const uint4*)(g_Wblo + n * FIN + k0 + c8);
            *(uint4*)(Bh + n * BST + c8) = vh;
            *(uint4*)(Bl + n * BST + c8) = vl;
        }
        __syncthreads();
        // ---- compute 4 x k16 ----
#pragma unroll
        for (int kk = 0; kk < 4; kk++) {
            int ko = kk * 16;
            const __nv_bfloat16* ar = Ah + (w * 16 + lq) * AST + ko + lr * 2;
            const __nv_bfloat16* al_ = Al + (w * 16 + lq) * AST + ko + lr * 2;
            uint32_t ah[4], alo[4];
            ah[0] = *(const uint32_t*)(ar);
            ah[1] = *(const uint32_t*)(ar + 8 * AST);
            ah[2] = *(const uint32_t*)(ar + 8);
            ah[3] = *(const uint32_t*)(ar + 8 * AST + 8);
            alo[0] = *(const uint32_t*)(al_);
            alo[1] = *(const uint32_t*)(al_ + 8 * AST);
            alo[2] = *(const uint32_t*)(al_ + 8);
            alo[3] = *(const uint32_t*)(al_ + 8 * AST + 8);
#pragma unroll
            for (int t = 0; t < 6; t++) {
                const __nv_bfloat16* br = Bh + (t * 8 + lq) * BST + ko + lr * 2;
                const __nv_bfloat16* bl_ = Bl + (t * 8 + lq) * BST + ko + lr * 2;
                uint32_t bh[2], blo[2];
                bh[0] = *(const uint32_t*)(br);
                bh[1] = *(const uint32_t*)(br + 8);
                blo[0] = *(const uint32_t*)(bl_);
                blo[1] = *(const uint32_t*)(bl_ + 8);
                MMA_BF16(acc[t], ah, bh);
                MMA_BF16(acc[t], ah, blo);
                MMA_BF16(acc[t], alo, bh);
            }
        }
        __syncthreads();
    }
    // ---- epilogue ----
    long r0 = mBase + w * 16 + lq;
#pragma unroll
    for (int t = 0; t < 6; t++) {
        int j = t * 8 + lr * 2;
        storeC(r0,     j,     acc[t][0]);
        storeC(r0,     j + 1, acc[t][1]);
        storeC(r0 + 8, j,     acc[t][2]);
        storeC(r0 + 8, j + 1, acc[t][3]);
    }
}

// ---------------- layer-1 aggregation + ELU (warp per node) ----------------
__global__ void k_agg1(const float* __restrict__ b1, float* __restrict__ x1out, int writeOut) {
    int w = (blockIdx.x * blockDim.x + threadIdx.x) >> 5;
    if (w >= NN) return;
    int lane = threadIdx.x & 31;
    int c = lane & 15;
    int h = lane >> 4;
    int start = g_rowptr[w];
    int deg = g_deg[w];
    float acc = 0.f;
    for (int e = start + h; e < start + deg; e += 2) {
        int2 r = g_esp[e];
        float p = __int_as_float(r.y);
        float2 y = *(const float2*)(g_Y + r.x * 32 + 2 * c);
        acc += fmaf(p, y.y - y.x, y.x);
    }
    acc += __shfl_down_sync(0xffffffffu, acc, 16);
    if (h == 0) {
        float v = fmaf(acc, g_invdeg[w], g_R[w * 16 + c] + b1[c]);
        v = (v > 0.f) ? v : expm1f(v);
        g_x1[w * 16 + c] = v;
        if (writeOut) x1out[w * 16 + c] = v;
    }
}

// ---------------- layer-2 aggregation in input space (warp per node) ----------------
__global__ void k_agg2() {
    int w = (blockIdx.x * blockDim.x + threadIdx.x) >> 5;
    if (w >= NN) return;
    int lane = threadIdx.x & 31;
    int c = lane & 15;
    int h = lane >> 4;
    int start = g_rowptr[w];
    int deg = g_deg[w];
    float accS = 0.f;
    float accB = 0.f;
    for (int e = start + h; e < start + deg; e += 2) {
        int2 r = g_esp[e];
        float p = __int_as_float(r.y);
        float xv = g_x1[r.x * 16 + c];
        accS += xv;
        accB = fmaf(p, xv, accB);
    }
    accS += __shfl_down_sync(0xffffffffu, accS, 16);
    accB += __shfl_down_sync(0xffffffffu, accB, 16);
    if (h == 0) {
        float inv = g_invdeg[w];
        g_AB[w * 32 + c]      = (accS - accB) * inv;
        g_AB[w * 32 + 16 + c] = accB * inv;
    }
}

// ---------------- GEMM2 + bias + log_softmax (thread per node) ----------------
__global__ __launch_bounds__(256) void k_out(const float* __restrict__ b2,
                                             float* __restrict__ out) {
    __shared__ float Ws[48 * NCLS];
    for (int i = threadIdx.x; i < 48 * NCLS; i += 256) Ws[i] = g_W2cat[i];
    __syncthreads();
    int node = blockIdx.x * 256 + threadIdx.x;
    if (node >= NN) return;

    float acc[NCLS];
#pragma unroll
    for (int cx = 0; cx < NCLS; cx++) acc[cx] = b2[cx];

    const float* ab = g_AB + node * 32;
#pragma unroll 4
    for (int r = 0; r < 32; r++) {
        float vv = ab[r];
        const float* wr = &Ws[r * NCLS];
#pragma unroll
        for (int cx = 0; cx < NCLS; cx++) acc[cx] = fmaf(vv, wr[cx], acc[cx]);
    }
    const float* xx = g_x1 + node * 16;
#pragma unroll 4
    for (int r = 0; r < 16; r++) {
        float vv = xx[r];
        const float* wr = &Ws[(32 + r) * NCLS];
#pragma unroll
        for (int cx = 0; cx < NCLS; cx++) acc[cx] = fmaf(vv, wr[cx], acc[cx]);
    }

    float m = acc[0];
#pragma unroll
    for (int cx = 1; cx < NCLS; cx++) m = fmaxf(m, acc[cx]);
    float ssum = 0.f;
#pragma unroll
    for (int cx = 0; cx < NCLS; cx++) ssum += expf(acc[cx] - m);
    float l = m + logf(ssum);
#pragma unroll
    for (int cx = 0; cx < NCLS; cx++) out[node * NCLS + cx] = acc[cx] - l;
}

// ---------------- launch ----------------
extern "C" void kernel_launch(void* const* d_in, const int* in_sizes, int n_in,
                              void* d_out, int out_size) {
    const float* x     = (const float*)d_in[0];
    const int*   ei    = (const int*)d_in[1];     // int32 (jax x64 disabled)
    const float* pa    = (const float*)d_in[2];
    const float* W1    = (const float*)d_in[3];
    const float* root1 = (const float*)d_in[4];
    const float* b1    = (const float*)d_in[5];
    const float* W2    = (const float*)d_in[6];
    const float* root2 = (const float*)d_in[7];
    const float* b2    = (const float*)d_in[8];
    float* out = (float*)d_out;

    int writeOut = (out_size >= NN * (NCLS + HID)) ? 1 : 0;
    float* x1out = out + (long)NN * NCLS;

    cudaFuncSetAttribute(k_gemm1_mma, cudaFuncAttributeMaxDynamicSharedMemorySize, G1_SMEM);

    k_zero_deg<<<(NN + 255) / 256, 256>>>();
    k_degree<<<NE / 256, 256>>>(ei);
    k_scan<<<1, 1024>>>();
    k_scatter<<<NE / 256, 256>>>(ei, pa);
    k_packW<<<(48 * FIN + 255) / 256, 256>>>(W1, root1);
    k_pack2<<<(48 * NCLS + 255) / 256, 256>>>(W2, root2);
    k_gemm1_mma<<<(NN + 127) / 128, 256, G1_SMEM>>>(x);
    k_agg1<<<NN / 8, 256>>>(b1, x1out, writeOut);
    k_agg2<<<NN / 8, 256>>>();
    k_out<<<(NN + 255) / 256, 256>>>(b2, out);
}

// round 6
// speedup vs baseline: 1.2653x; 1.1145x over previous
#include <cuda_runtime.h>
#include <cuda_bf16.h>
#include <cstdint>

#define NN   100000
#define NE   3200000
#define FIN  1024
#define HID  16
#define NCLS 40

// ---------------- device scratch ----------------
__device__ int    g_deg[NN];
__device__ float  g_invdeg[NN];
__device__ int    g_rowptr[NN + 1];
__device__ int    g_cursor[NN];
__device__ __align__(16) int2  g_esp[NE];          // (src, p-bits) per CSR slot
__device__ __align__(16) float g_Y[NN * 32];       // per-node interleaved [y0_c, y1_c] x16
__device__ __align__(16) float g_R[NN * 16];       // x@root1
__device__ __align__(16) __nv_bfloat16 g_Wbhi[48 * FIN];  // [n][k] hi split
__device__ __align__(16) __nv_bfloat16 g_Wblo[48 * FIN];  // [n][k] lo split
__device__ float  g_W2cat[48 * NCLS];
__device__ __align__(16) float g_AB[NN * 32];
__device__ __align__(16) float g_x1[NN * HID];

__device__ __forceinline__ int clampN(int v) {
    v = v < 0 ? 0 : v;
    return v >= NN ? NN - 1 : v;
}

__device__ __forceinline__ uint32_t smem_u32(const void* p) {
    uint32_t a;
    asm("{ .reg .u64 t; cvta.to.shared.u64 t, %1; cvt.u32.u64 %0, t; }" : "=r"(a) : "l"(p));
    return a;
}

// ---------------- CSR build ----------------
__global__ void k_zero_deg() {
    int i = blockIdx.x * blockDim.x + threadIdx.x;
    if (i < NN) g_deg[i] = 0;
}

__global__ void k_degree4(const int* __restrict__ ei) {
    int t = blockIdx.x * blockDim.x + threadIdx.x;
    if (t >= NE / 4) return;
    int4 d4 = ((const int4*)(ei + NE))[t];
    atomicAdd(&g_deg[clampN(d4.x)], 1);
    atomicAdd(&g_deg[clampN(d4.y)], 1);
    atomicAdd(&g_deg[clampN(d4.z)], 1);
    atomicAdd(&g_deg[clampN(d4.w)], 1);
}

__global__ void k_scan() {
    __shared__ int ss[1024];
    int tid = threadIdx.x;
    const int per = (NN + 1023) / 1024;
    int start = tid * per;
    int end = start + per; if (end > NN) end = NN;
    if (start > NN) start = NN;
    int s = 0;
    for (int i = start; i < end; i++) s += g_deg[i];
    ss[tid] = s;
    __syncthreads();
    for (int off = 1; off < 1024; off <<= 1) {
        int add = (tid >= off) ? ss[tid - off] : 0;
        __syncthreads();
        ss[tid] += add;
        __syncthreads();
    }
    int run = (tid > 0) ? ss[tid - 1] : 0;
    for (int i = start; i < end; i++) {
        int d = g_deg[i];
        g_rowptr[i] = run;
        g_cursor[i] = run;
        g_invdeg[i] = 1.0f / (float)(d > 0 ? d : 1);
        run += d;
    }
    if (tid == 1023) g_rowptr[NN] = run;
}

__global__ void k_scatter4(const int* __restrict__ ei, const float* __restrict__ pa) {
    int t = blockIdx.x * blockDim.x + threadIdx.x;
    if (t >= NE / 4) return;
    int4   s4 = ((const int4*)ei)[t];
    int4   d4 = ((const int4*)(ei + NE))[t];
    float4 p4 = ((const float4*)pa)[t];
    int p0 = atomicAdd(&g_cursor[clampN(d4.x)], 1);
    int p1 = atomicAdd(&g_cursor[clampN(d4.y)], 1);
    int p2 = atomicAdd(&g_cursor[clampN(d4.z)], 1);
    int p3 = atomicAdd(&g_cursor[clampN(d4.w)], 1);
    if ((unsigned)p0 < NE) g_esp[p0] = make_int2(clampN(s4.x), __float_as_int(p4.x));
    if ((unsigned)p1 < NE) g_esp[p1] = make_int2(clampN(s4.y), __float_as_int(p4.y));
    if ((unsigned)p2 < NE) g_esp[p2] = make_int2(clampN(s4.z), __float_as_int(p4.z));
    if ((unsigned)p3 < NE) g_esp[p3] = make_int2(clampN(s4.w), __float_as_int(p4.w));
}

// ---------------- weight packing (bf16 hi/lo split, [n][k]) ----------------
__global__ void k_packW(const float* __restrict__ W1, const float* __restrict__ root1) {
    int idx = blockIdx.x * blockDim.x + threadIdx.x;
    if (idx >= 48 * FIN) return;
    int n = idx >> 10, k = idx & 1023;
    float v;
    if (n < 16)      v = W1[k * 16 + n];
    else if (n < 32) v = W1[FIN * 16 + k * 16 + (n - 16)];
    else             v = root1[k * 16 + (n - 32)];
    __nv_bfloat16 h = __float2bfloat16(v);
    __nv_bfloat16 l = __float2bfloat16(v - __bfloat162float(h));
    g_Wbhi[idx] = h;
    g_Wblo[idx] = l;
}

__global__ void k_pack2(const float* __restrict__ W2, const float* __restrict__ root2) {
    int idx = blockIdx.x * blockDim.x + threadIdx.x;
    if (idx >= 48 * NCLS) return;
    int r = idx / NCLS, c = idx % NCLS;
    float v;
    if (r < 16)      v = W2[r * NCLS + c];
    else if (r < 32) v = W2[16 * NCLS + (r - 16) * NCLS + c];
    else             v = root2[(r - 32) * NCLS + c];
    g_W2cat[idx] = v;
}

// ---------------- GEMM1 via mma.sync bf16 (double split), pipelined ----------------
// CTA: 256 thr / 8 warps. M=128 (16 rows/warp), N=48 (6 n8 tiles), K-chunk 32, 32 chunks,
// double-buffered SMEM + register prefetch, ldmatrix operand loads.
#define AST 40
#define BST 40
#define A_BYTES (128 * AST * 2)                 // 10240 (per Ah or Al)
#define B_BYTES (48 * BST * 2)                  // 3840
#define BUF_BYTES (2 * A_BYTES + 2 * B_BYTES)   // 28160
#define G1_SMEM (2 * BUF_BYTES)                 // 56320

#define MMA_BF16(d, a0, a1, a2, a3, b0, b1) \
    asm volatile("mma.sync.aligned.m16n8k16.row.col.f32.bf16.bf16.f32 " \
        "{%0,%1,%2,%3}, {%4,%5,%6,%7}, {%8,%9}, {%0,%1,%2,%3};" \
        : "+f"((d)[0]), "+f"((d)[1]), "+f"((d)[2]), "+f"((d)[3]) \
        : "r"(a0), "r"(a1), "r"(a2), "r"(a3), "r"(b0), "r"(b1))

#define LDSM_X4(r0, r1, r2, r3, addr) \
    asm volatile("ldmatrix.sync.aligned.m8n8.x4.shared.b16 {%0,%1,%2,%3}, [%4];" \
        : "=r"(r0), "=r"(r1), "=r"(r2), "=r"(r3) : "r"(addr))

__device__ __forceinline__ uint32_t split_hi(float a, float b, uint32_t& lo) {
    __nv_bfloat162 h = __floats2bfloat162_rn(a, b);
    float ra = a - __low2float(h);
    float rb = b - __high2float(h);
    __nv_bfloat162 L = __floats2bfloat162_rn(ra, rb);
    lo = *(uint32_t*)&L;
    return *(uint32_t*)&h;
}

__device__ __forceinline__ void storeC(long row, int j, float v) {
    if (row >= NN) return;
    if (j < 16)      g_Y[row * 32 + 2 * j] = v;
    else if (j < 32) g_Y[row * 32 + 2 * (j - 16) + 1] = v;
    else             g_R[row * 16 + (j - 32)] = v;
}

__device__ __forceinline__ void g1_loadA(const float* __restrict__ x, long mBase,
                                         int tid, int k0, float4 va[4]) {
#pragma unroll
    for (int i = 0; i < 4; i++) {
        int idx = tid + i * 256;
        int r = idx >> 3, c4 = (idx & 7) * 4;
        long gr = mBase + r;
        va[i] = (gr < NN) ? *(const float4*)(x + gr * FIN + k0 + c4)
                          : make_float4(0.f, 0.f, 0.f, 0.f);
    }
}

__device__ __forceinline__ void g1_storeA(char* bufA, int tid, const float4 va[4]) {
    __nv_bfloat16* Ah = (__nv_bfloat16*)bufA;
    __nv_bfloat16* Al = (__nv_bfloat16*)(bufA + A_BYTES);
#pragma unroll
    for (int i = 0; i < 4; i++) {
        int idx = tid + i * 256;
        int r = idx >> 3, c4 = (idx & 7) * 4;
        uint32_t l0, l1;
        uint32_t h0 = split_hi(va[i].x, va[i].y, l0);
        uint32_t h1 = split_hi(va[i].z, va[i].w, l1);
        *(uint2*)(Ah + r * AST + c4) = make_uint2(h0, h1);
        *(uint2*)(Al + r * AST + c4) = make_uint2(l0, l1);
    }
}

__global__ __launch_bounds__(256, 2) void k_gemm1_mma(const float* __restrict__ x) {
    extern __shared__ __align__(16) char sm[];
    int tid = threadIdx.x, w = tid >> 5, l = tid & 31;
    int lq = l >> 2, lr = l & 3;
    long mBase = (long)blockIdx.x * 128;
    uint32_t smb = smem_u32(sm);

    // ldmatrix lane address offsets
    int m_off  = (l & 7) + ((l & 8) ? 8 : 0);
    int kA_off = (l & 16) ? 8 : 0;
    uint32_t aoff = ((w * 16 + m_off) * AST + kA_off) * 2;
    int n_off  = (l & 7) + ((l & 16) ? 8 : 0);
    int kB_off = (l & 8) ? 8 : 0;
    uint32_t boff0 = ((0 * 16 + n_off) * BST + kB_off) * 2;
    uint32_t boff1 = ((1 * 16 + n_off) * BST + kB_off) * 2;
    uint32_t boff2 = ((2 * 16 + n_off) * BST + kB_off) * 2;

    float acc[6][4];
#pragma unroll
    for (int t = 0; t < 6; t++)
#pragma unroll
        for (int i = 0; i < 4; i++) acc[t][i] = 0.f;

    float4 va[4];
    uint4 vbh, vbl;
    // prologue: chunk 0
    g1_loadA(x, mBase, tid, 0, va);
    if (tid < 192) {
        int n = tid >> 2, c8 = (tid & 3) * 8;
        vbh = *(const uint4*)(g_Wbhi + n * FIN + 0 + c8);
        vbl = *(const uint4*)(g_Wblo + n * FIN + 0 + c8);
    }
    g1_storeA(sm, tid, va);
    if (tid < 192) {
        int n = tid >> 2, c8 = (tid & 3) * 8;
        *(uint4*)(sm + 2 * A_BYTES + (n * BST + c8) * 2) = vbh;
        *(uint4*)(sm + 2 * A_BYTES + B_BYTES + (n * BST + c8) * 2) = vbl;
    }
    __syncthreads();

    for (int kb = 0; kb < 32; kb++) {
        uint32_t base = smb + (kb & 1) * BUF_BYTES;
        bool more = (kb < 31);
        if (more) {
            int k0 = (kb + 1) * 32;
            g1_loadA(x, mBase, tid, k0, va);
            if (tid < 192) {
                int n = tid >> 2, c8 = (tid & 3) * 8;
                vbh = *(const uint4*)(g_Wbhi + n * FIN + k0 + c8);
                vbl = *(const uint4*)(g_Wblo + n * FIN + k0 + c8);
            }
        }
        uint32_t ahb = base + aoff;
        uint32_t alb = base + A_BYTES + aoff;
        uint32_t bhb = base + 2 * A_BYTES;
        uint32_t blb = base + 2 * A_BYTES + B_BYTES;
#pragma unroll
        for (int kk = 0; kk < 2; kk++) {
            uint32_t ko2 = kk * 16 * 2;
            uint32_t ah0, ah1, ah2, ah3, al0, al1, al2, al3;
            LDSM_X4(ah0, ah1, ah2, ah3, ahb + ko2);
            LDSM_X4(al0, al1, al2, al3, alb + ko2);
            uint32_t bofs[3] = {boff0, boff1, boff2};
#pragma unroll
            for (int tp = 0; tp < 3; tp++) {
                uint32_t bh0, bh1, bh2, bh3, bl0, bl1, bl2, bl3;
                LDSM_X4(bh0, bh1, bh2, bh3, bhb + bofs[tp] + ko2);
                LDSM_X4(bl0, bl1, bl2, bl3, blb + bofs[tp] + ko2);
                MMA_BF16(acc[2 * tp],     ah0, ah1, ah2, ah3, bh0, bh1);
                MMA_BF16(acc[2 * tp],     ah0, ah1, ah2, ah3, bl0, bl1);
                MMA_BF16(acc[2 * tp],     al0, al1, al2, al3, bh0, bh1);
                MMA_BF16(acc[2 * tp + 1], ah0, ah1, ah2, ah3, bh2, bh3);
                MMA_BF16(acc[2 * tp + 1], ah0, ah1, ah2, ah3, bl2, bl3);
                MMA_BF16(acc[2 * tp + 1], al0, al1, al2, al3, bh2, bh3);
            }
        }
        if (more) {
            char* nb = sm + ((kb + 1) & 1) * BUF_BYTES;
            g1_storeA(nb, tid, va);
            if (tid < 192) {
                int n = tid >> 2, c8 = (tid & 3) * 8;
                *(uint4*)(nb + 2 * A_BYTES + (n * BST + c8) * 2) = vbh;
                *(uint4*)(nb + 2 * A_BYTES + B_BYTES + (n * BST + c8) * 2) = vbl;
            }
            __syncthreads();
        }
    }
    // epilogue
    long r0 = mBase + w * 16 + lq;
#pragma unroll
    for (int t = 0; t < 6; t++) {
        int j = t * 8 + lr * 2;
        storeC(r0,     j,     acc[t][0]);
        storeC(r0,     j + 1, acc[t][1]);
        storeC(r0 + 8, j,     acc[t][2]);
        storeC(r0 + 8, j + 1, acc[t][3]);
    }
}

// ---------------- layer-1 aggregation + ELU (warp per node) ----------------
__global__ void k_agg1(const float* __restrict__ b1, float* __restrict__ x1out, int writeOut) {
    int w = (blockIdx.x * blockDim.x + threadIdx.x) >> 5;
    if (w >= NN) return;
    int lane = threadIdx.x & 31;
    int c = lane & 15;
    int h = lane >> 4;
    int start = g_rowptr[w];
    int end = start + g_deg[w];
    float acc = 0.f, accb = 0.f;
    int e = start + h;
    for (; e + 2 < end; e += 4) {
        int2 r0 = g_esp[e];
        int2 r1 = g_esp[e + 2];
        float p0 = __int_as_float(r0.y);
        float p1 = __int_as_float(r1.y);
        float2 y0 = *(const float2*)(g_Y + r0.x * 32 + 2 * c);
        float2 y1 = *(const float2*)(g_Y + r1.x * 32 + 2 * c);
        acc  += fmaf(p0, y0.y - y0.x, y0.x);
        accb += fmaf(p1, y1.y - y1.x, y1.x);
    }
    for (; e < end; e += 2) {
        int2 r0 = g_esp[e];
        float p0 = __int_as_float(r0.y);
        float2 y0 = *(const float2*)(g_Y + r0.x * 32 + 2 * c);
        acc += fmaf(p0, y0.y - y0.x, y0.x);
    }
    acc += accb;
    acc += __shfl_down_sync(0xffffffffu, acc, 16);
    if (h == 0) {
        float v = fmaf(acc, g_invdeg[w], g_R[w * 16 + c] + b1[c]);
        v = (v > 0.f) ? v : expm1f(v);
        g_x1[w * 16 + c] = v;
        if (writeOut) x1out[w * 16 + c] = v;
    }
}

// ---------------- layer-2 aggregation in input space (warp per node) ----------------
__global__ void k_agg2() {
    int w = (blockIdx.x * blockDim.x + threadIdx.x) >> 5;
    if (w >= NN) return;
    int lane = threadIdx.x & 31;
    int c = lane & 15;
    int h = lane >> 4;
    int start = g_rowptr[w];
    int end = start + g_deg[w];
    float accS = 0.f, accB = 0.f, accS2 = 0.f, accB2 = 0.f;
    int e = start + h;
    for (; e + 2 < end; e += 4) {
        int2 r0 = g_esp[e];
        int2 r1 = g_esp[e + 2];
        float p0 = __int_as_float(r0.y);
        float p1 = __int_as_float(r1.y);
        float x0 = g_x1[r0.x * 16 + c];
        float x1v = g_x1[r1.x * 16 + c];
        accS += x0;              accS2 += x1v;
        accB = fmaf(p0, x0, accB); accB2 = fmaf(p1, x1v, accB2);
    }
    for (; e < end; e += 2) {
        int2 r0 = g_esp[e];
        float p0 = __int_as_float(r0.y);
        float x0 = g_x1[r0.x * 16 + c];
        accS += x0;
        accB = fmaf(p0, x0, accB);
    }
    accS += accS2; accB += accB2;
    accS += __shfl_down_sync(0xffffffffu, accS, 16);
    accB += __shfl_down_sync(0xffffffffu, accB, 16);
    if (h == 0) {
        float inv = g_invdeg[w];
        g_AB[w * 32 + c]      = (accS - accB) * inv;
        g_AB[w * 32 + 16 + c] = accB * inv;
    }
}

// ---------------- GEMM2 + bias + log_softmax (thread per node) ----------------
__global__ __launch_bounds__(256) void k_out(const float* __restrict__ b2,
                                             float* __restrict__ out) {
    __shared__ float Ws[48 * NCLS];
    for (int i = threadIdx.x; i < 48 * NCLS; i += 256) Ws[i] = g_W2cat[i];
    __syncthreads();
    int node = blockIdx.x * 256 + threadIdx.x;
    if (node >= NN) return;

    float acc[NCLS];
#pragma unroll
    for (int cx = 0; cx < NCLS; cx++) acc[cx] = b2[cx];

    const float* ab = g_AB + node * 32;
#pragma unroll 4
    for (int r = 0; r < 32; r++) {
        float vv = ab[r];
        const float* wr = &Ws[r * NCLS];
#pragma unroll
        for (int cx = 0; cx < NCLS; cx++) acc[cx] = fmaf(vv, wr[cx], acc[cx]);
    }
    const float* xx = g_x1 + node * 16;
#pragma unroll 4
    for (int r = 0; r < 16; r++) {
        float vv = xx[r];
        const float* wr = &Ws[(32 + r) * NCLS];
#pragma unroll
        for (int cx = 0; cx < NCLS; cx++) acc[cx] = fmaf(vv, wr[cx], acc[cx]);
    }

    float m = acc[0];
#pragma unroll
    for (int cx = 1; cx < NCLS; cx++) m = fmaxf(m, acc[cx]);
    float ssum = 0.f;
#pragma unroll
    for (int cx = 0; cx < NCLS; cx++) ssum += expf(acc[cx] - m);
    float l = m + logf(ssum);
#pragma unroll
    for (int cx = 0; cx < NCLS; cx++) out[node * NCLS + cx] = acc[cx] - l;
}

// ---------------- launch ----------------
extern "C" void kernel_launch(void* const* d_in, const int* in_sizes, int n_in,
                              void* d_out, int out_size) {
    const float* x     = (const float*)d_in[0];
    const int*   ei    = (const int*)d_in[1];     // int32 (jax x64 disabled)
    const float* pa    = (const float*)d_in[2];
    const float* W1    = (const float*)d_in[3];
    const float* root1 = (const float*)d_in[4];
    const float* b1    = (const float*)d_in[5];
    const float* W2    = (const float*)d_in[6];
    const float* root2 = (const float*)d_in[7];
    const float* b2    = (const float*)d_in[8];
    float* out = (float*)d_out;

    int writeOut = (out_size >= NN * (NCLS + HID)) ? 1 : 0;
    float* x1out = out + (long)NN * NCLS;

    cudaFuncSetAttribute(k_gemm1_mma, cudaFuncAttributeMaxDynamicSharedMemorySize, G1_SMEM);

    // order chosen so k_gemm1_mma is the 4th launch (the slot ncu captures)
    k_packW<<<(48 * FIN + 255) / 256, 256>>>(W1, root1);
    k_zero_deg<<<(NN + 255) / 256, 256>>>();
    k_degree4<<<(NE / 4 + 255) / 256, 256>>>(ei);
    k_gemm1_mma<<<(NN + 127) / 128, 256, G1_SMEM>>>(x);
    k_scan<<<1, 1024>>>();
    k_scatter4<<<(NE / 4 + 255) / 256, 256>>>(ei, pa);
    k_pack2<<<(48 * NCLS + 255) / 256, 256>>>(W2, root2);
    k_agg1<<<NN / 8, 256>>>(b1, x1out, writeOut);
    k_agg2<<<NN / 8, 256>>>();
    k_out<<<(NN + 255) / 256, 256>>>(b2, out);
}

// round 8
// speedup vs baseline: 1.7420x; 1.3767x over previous
#include <cuda_runtime.h>
#include <cuda_bf16.h>
#include <cstdint>

#define NN   100000
#define NE   3200000
#define FIN  1024
#define HID  16
#define NCLS 40

// ---------------- device scratch ----------------
__device__ int    g_deg[NN];
__device__ __align__(16) float g_Y[NN * 32];       // per-node interleaved [y0_c, y1_c] x16
__device__ __align__(16) float g_R[NN * 16];       // x@root1
__device__ __align__(16) float g_S1[NN * 16];      // layer-1 message sums
__device__ __align__(16) __nv_bfloat16 g_Wbhi[48 * FIN];  // [n][k] hi split
__device__ __align__(16) __nv_bfloat16 g_Wblo[48 * FIN];  // [n][k] lo split
__device__ float  g_W2cat[48 * NCLS];
__device__ __align__(16) float g_AB[NN * 32];      // [A(16) | B(16)] raw sums
__device__ __align__(16) float g_x1[NN * HID];

__device__ __forceinline__ int clampN(int v) {
    v = v < 0 ? 0 : v;
    return v >= NN ? NN - 1 : v;
}

__device__ __forceinline__ uint32_t smem_u32(const void* p) {
    uint32_t a;
    asm("{ .reg .u64 t; cvta.to.shared.u64 t, %1; cvt.u32.u64 %0, t; }" : "=r"(a) : "l"(p));
    return a;
}

// ---------------- zero (S1 + deg) ----------------
__global__ void k_zero() {
    int t = blockIdx.x * blockDim.x + threadIdx.x;
    if (t < NN * 4) ((float4*)g_S1)[t] = make_float4(0.f, 0.f, 0.f, 0.f);
    if (t < NN) g_deg[t] = 0;
}

// ---------------- weight packing ----------------
__global__ void k_packW(const float* __restrict__ W1, const float* __restrict__ root1) {
    int idx = blockIdx.x * blockDim.x + threadIdx.x;
    if (idx >= 48 * FIN) return;
    int n = idx >> 10, k = idx & 1023;
    float v;
    if (n < 16)      v = W1[k * 16 + n];
    else if (n < 32) v = W1[FIN * 16 + k * 16 + (n - 16)];
    else             v = root1[k * 16 + (n - 32)];
    __nv_bfloat16 h = __float2bfloat16(v);
    __nv_bfloat16 l = __float2bfloat16(v - __bfloat162float(h));
    g_Wbhi[idx] = h;
    g_Wblo[idx] = l;
}

__global__ void k_pack2(const float* __restrict__ W2, const float* __restrict__ root2) {
    int idx = blockIdx.x * blockDim.x + threadIdx.x;
    if (idx >= 48 * NCLS) return;
    int r = idx / NCLS, c = idx % NCLS;
    float v;
    if (r < 16)      v = W2[r * NCLS + c];
    else if (r < 32) v = W2[16 * NCLS + (r - 16) * NCLS + c];
    else             v = root2[(r - 32) * NCLS + c];
    g_W2cat[idx] = v;
}

// ---------------- GEMM1: A direct-from-gmem fragments, B in SMEM ----------------
// CTA 256 thr / 8 warps, M=128 (16 rows/warp), N=48 (6 n8 tiles), K-chunk 64.
#define BST 72   // B smem row stride (bf16 elems); 144B = 9*16B, ldmatrix conflict-free

#define MMA_BF16(d, a0, a1, a2, a3, b0, b1) \
    asm volatile("mma.sync.aligned.m16n8k16.row.col.f32.bf16.bf16.f32 " \
        "{%0,%1,%2,%3}, {%4,%5,%6,%7}, {%8,%9}, {%0,%1,%2,%3};" \
        : "+f"((d)[0]), "+f"((d)[1]), "+f"((d)[2]), "+f"((d)[3]) \
        : "r"(a0), "r"(a1), "r"(a2), "r"(a3), "r"(b0), "r"(b1))

#define LDSM_X4(r0, r1, r2, r3, addr) \
    asm volatile("ldmatrix.sync.aligned.m8n8.x4.shared.b16 {%0,%1,%2,%3}, [%4];" \
        : "=r"(r0), "=r"(r1), "=r"(r2), "=r"(r3) : "r"(addr))

__device__ __forceinline__ uint32_t split_hi(float a, float b, uint32_t& lo) {
    __nv_bfloat162 h = __floats2bfloat162_rn(a, b);
    float ra = a - __low2float(h);
    float rb = b - __high2float(h);
    __nv_bfloat162 L = __floats2bfloat162_rn(ra, rb);
    lo = *(uint32_t*)&L;
    return *(uint32_t*)&h;
}

__device__ __forceinline__ void storeC(long row, int j, float v) {
    if (row >= NN) return;
    if (j < 16)      g_Y[row * 32 + 2 * j] = v;
    else if (j < 32) g_Y[row * 32 + 2 * (j - 16) + 1] = v;
    else             g_R[row * 16 + (j - 32)] = v;
}

__global__ __launch_bounds__(256, 3) void k_gemm1_mma(const float* __restrict__ x) {
    __shared__ __align__(16) __nv_bfloat16 Bs[2][48 * BST];  // [hi|lo]
    int tid = threadIdx.x, w = tid >> 5, l = tid & 31;
    int lq = l >> 2, lr = l & 3;
    long mBase = (long)blockIdx.x * 128;

    long rA = mBase + w * 16 + lq;
    long rA0 = rA < NN ? rA : NN - 1;
    long rA1 = (rA + 8) < NN ? (rA + 8) : NN - 1;
    const float* xr0 = x + rA0 * FIN + 2 * lr;
    const float* xr1 = x + rA1 * FIN + 2 * lr;

    uint32_t bs_hi = smem_u32(&Bs[0][0]);
    uint32_t bs_lo = smem_u32(&Bs[1][0]);
    int n_off = (l & 7) + ((l & 16) ? 8 : 0);
    int kB_off = (l & 8) ? 8 : 0;
    uint32_t bo0 = ((0 * 16 + n_off) * BST + kB_off) * 2;
    uint32_t bo1 = ((1 * 16 + n_off) * BST + kB_off) * 2;
    uint32_t bo2 = ((2 * 16 + n_off) * BST + kB_off) * 2;

    float acc[6][4];
#pragma unroll
    for (int t = 0; t < 6; t++)
#pragma unroll
        for (int i = 0; i < 4; i++) acc[t][i] = 0.f;

    for (int kb = 0; kb < 16; kb++) {
        int k0 = kb * 64;
        __syncthreads();
        // load B chunk (48 x 64, hi+lo)
#pragma unroll
        for (int i = tid; i < 384; i += 256) {
            int n = i >> 3, c8 = (i & 7) * 8;
            uint4 vh = *(const uint4*)(g_Wbhi + n * FIN + k0 + c8);
            uint4 vl = *(const uint4*)(g_Wblo + n * FIN + k0 + c8);
            *(uint4*)&Bs[0][n * BST + c8] = vh;
            *(uint4*)&Bs[1][n * BST + c8] = vl;
        }
        __syncthreads();
#pragma unroll
        for (int ks = 0; ks < 4; ks++) {
            int kc = k0 + ks * 16;
            float2 v00 = *(const float2*)(xr0 + kc);
            float2 v10 = *(const float2*)(xr1 + kc);
            float2 v01 = *(const float2*)(xr0 + kc + 8);
            float2 v11 = *(const float2*)(xr1 + kc + 8);
            uint32_t al0, al1, al2, al3;
            uint32_t ah0 = split_hi(v00.x, v00.y, al0);
            uint32_t ah1 = split_hi(v10.x, v10.y, al1);
            uint32_t ah2 = split_hi(v01.x, v01.y, al2);
            uint32_t ah3 = split_hi(v11.x, v11.y, al3);
            uint32_t ko = ks * 32;
            uint32_t bofs[3] = {bo0, bo1, bo2};
#pragma unroll
            for (int tp = 0; tp < 3; tp++) {
                uint32_t bh0, bh1, bh2, bh3, bl0, bl1, bl2, bl3;
                LDSM_X4(bh0, bh1, bh2, bh3, bs_hi + bofs[tp] + ko);
                LDSM_X4(bl0, bl1, bl2, bl3, bs_lo + bofs[tp] + ko);
                MMA_BF16(acc[2 * tp],     ah0, ah1, ah2, ah3, bh0, bh1);
                MMA_BF16(acc[2 * tp],     ah0, ah1, ah2, ah3, bl0, bl1);
                MMA_BF16(acc[2 * tp],     al0, al1, al2, al3, bh0, bh1);
                MMA_BF16(acc[2 * tp + 1], ah0, ah1, ah2, ah3, bh2, bh3);
                MMA_BF16(acc[2 * tp + 1], ah0, ah1, ah2, ah3, bl2, bl3);
                MMA_BF16(acc[2 * tp + 1], al0, al1, al2, al3, bh2, bh3);
            }
        }
    }
    long r0 = mBase + w * 16 + lq;
#pragma unroll
    for (int t = 0; t < 6; t++) {
        int j = t * 8 + lr * 2;
        storeC(r0,     j,     acc[t][0]);
        storeC(r0,     j + 1, acc[t][1]);
        storeC(r0 + 8, j,     acc[t][2]);
        storeC(r0 + 8, j + 1, acc[t][3]);
    }
}

// ---------------- layer-1 edge aggregation (atomic), degree folded in ----------------
// thread = (edge, channel-pair): 8 threads per edge, 2 channels each
__global__ __launch_bounds__(256) void k_edge1(const int* __restrict__ ei,
                                               const float* __restrict__ pa) {
    int t = blockIdx.x * 256 + threadIdx.x;
    int e = t >> 3;
    if (e >= NE) return;
    int c2 = t & 7;
    int src = clampN(ei[e]);
    int dst = clampN(ei[NE + e]);
    float p = pa[e];
    float4 y = *(const float4*)(g_Y + src * 32 + 4 * c2);
    float m0 = fmaf(p, y.y - y.x, y.x);
    float m1 = fmaf(p, y.w - y.z, y.z);
    atomicAdd(&g_S1[dst * 16 + 2 * c2],     m0);
    atomicAdd(&g_S1[dst * 16 + 2 * c2 + 1], m1);
    if (c2 == 0) atomicAdd(&g_deg[dst], 1);
}

// ---------------- node update: x1 = elu(S1/deg + R + b1); zero AB ----------------
__global__ __launch_bounds__(256) void k_node1(const float* __restrict__ b1,
                                               float* __restrict__ x1out, int writeOut) {
    int t = blockIdx.x * 256 + threadIdx.x;
    int node = t >> 4;
    if (node >= NN) return;
    int c = t & 15;
    int deg = g_deg[node];
    float inv = 1.f / (float)(deg > 0 ? deg : 1);
    float v = fmaf(g_S1[node * 16 + c], inv, g_R[node * 16 + c] + b1[c]);
    v = (v > 0.f) ? v : expm1f(v);
    g_x1[node * 16 + c] = v;
    if (writeOut) x1out[node * 16 + c] = v;
    g_AB[node * 32 + c] = 0.f;
    g_AB[node * 32 + 16 + c] = 0.f;
}

// ---------------- layer-2 edge aggregation (atomic) ----------------
__global__ __launch_bounds__(256) void k_edge2(const int* __restrict__ ei,
                                               const float* __restrict__ pa) {
    int t = blockIdx.x * 256 + threadIdx.x;
    int e = t >> 3;
    if (e >= NE) return;
    int c2 = t & 7;
    int src = clampN(ei[e]);
    int dst = clampN(ei[NE + e]);
    float p = pa[e];
    float2 xv = *(const float2*)(g_x1 + src * 16 + 2 * c2);
    float q = 1.f - p;
    atomicAdd(&g_AB[dst * 32 + 2 * c2],          q * xv.x);
    atomicAdd(&g_AB[dst * 32 + 2 * c2 + 1],      q * xv.y);
    atomicAdd(&g_AB[dst * 32 + 16 + 2 * c2],     p * xv.x);
    atomicAdd(&g_AB[dst * 32 + 16 + 2 * c2 + 1], p * xv.y);
}

// ---------------- GEMM2 + bias + log_softmax (thread per node) ----------------
__global__ __launch_bounds__(256) void k_out(const float* __restrict__ b2,
                                             float* __restrict__ out) {
    __shared__ float Ws[48 * NCLS];
    for (int i = threadIdx.x; i < 48 * NCLS; i += 256) Ws[i] = g_W2cat[i];
    __syncthreads();
    int node = blockIdx.x * 256 + threadIdx.x;
    if (node >= NN) return;

    int deg = g_deg[node];
    float inv = 1.f / (float)(deg > 0 ? deg : 1);

    float acc[NCLS];
#pragma unroll
    for (int cx = 0; cx < NCLS; cx++) acc[cx] = b2[cx];

    const float* ab = g_AB + node * 32;
#pragma unroll 4
    for (int r = 0; r < 32; r++) {
        float vv = ab[r] * inv;
        const float* wr = &Ws[r * NCLS];
#pragma unroll
        for (int cx = 0; cx < NCLS; cx++) acc[cx] = fmaf(vv, wr[cx], acc[cx]);
    }
    const float* xx = g_x1 + node * 16;
#pragma unroll 4
    for (int r = 0; r < 16; r++) {
        float vv = xx[r];
        const float* wr = &Ws[(32 + r) * NCLS];
#pragma unroll
        for (int cx = 0; cx < NCLS; cx++) acc[cx] = fmaf(vv, wr[cx], acc[cx]);
    }

    float m = acc[0];
#pragma unroll
    for (int cx = 1; cx < NCLS; cx++) m = fmaxf(m, acc[cx]);
    float ssum = 0.f;
#pragma unroll
    for (int cx = 0; cx < NCLS; cx++) ssum += expf(acc[cx] - m);
    float l = m + logf(ssum);
#pragma unroll
    for (int cx = 0; cx < NCLS; cx++) out[node * NCLS + cx] = acc[cx] - l;
}

// ---------------- launch ----------------
extern "C" void kernel_launch(void* const* d_in, const int* in_sizes, int n_in,
                              void* d_out, int out_size) {
    const float* x     = (const float*)d_in[0];
    const int*   ei    = (const int*)d_in[1];     // int32 (jax x64 disabled)
    const float* pa    = (const float*)d_in[2];
    const float* W1    = (const float*)d_in[3];
    const float* root1 = (const float*)d_in[4];
    const float* b1    = (const float*)d_in[5];
    const float* W2    = (const float*)d_in[6];
    const float* root2 = (const float*)d_in[7];
    const float* b2    = (const float*)d_in[8];
    float* out = (float*)d_out;

    int writeOut = (out_size >= NN * (NCLS + HID)) ? 1 : 0;
    float* x1out = out + (long)NN * NCLS;

    // order: k_edge1 is the 4th launch (profiled slot)
    k_packW<<<(48 * FIN + 255) / 256, 256>>>(W1, root1);
    k_zero<<<(NN * 4 + 255) / 256, 256>>>();
    k_gemm1_mma<<<(NN + 127) / 128, 256>>>(x);
    k_edge1<<<(NE * 8) / 256, 256>>>(ei, pa);
    k_node1<<<(NN * 16 + 255) / 256, 256>>>(b1, x1out, writeOut);
    k_edge2<<<(NE * 8) / 256, 256>>>(ei, pa);
    k_pack2<<<(48 * NCLS + 255) / 256, 256>>>(W2, root2);
    k_out<<<(NN + 255) / 256, 256>>>(b2, out);
}

// round 10
// speedup vs baseline: 1.9365x; 1.1117x over previous
#include <cuda_runtime.h>
#include <cuda_bf16.h>
#include <cstdint>

#define NN   100000
#define NE   3200000
#define FIN  1024
#define HID  16
#define NCLS 40

// ---------------- device scratch ----------------
__device__ int    g_deg[NN];
__device__ __align__(16) float g_Y[NN * 32];       // per-node interleaved [y0_c, y1_c] x16
__device__ __align__(16) float g_R[NN * 16];       // x@root1
__device__ __align__(16) float g_S1[NN * 16];      // layer-1 message sums
__device__ __align__(16) __nv_bfloat16 g_Wbhi[48 * FIN];  // [n][k] hi split
__device__ __align__(16) __nv_bfloat16 g_Wblo[48 * FIN];  // [n][k] lo split
__device__ float  g_W2cat[48 * NCLS];
__device__ __align__(16) float g_AB[NN * 32];      // per node, channel-interleaved [A_c, B_c] x16
__device__ __align__(16) float g_x1[NN * HID];

__device__ __forceinline__ int clampN(int v) {
    v = v < 0 ? 0 : v;
    return v >= NN ? NN - 1 : v;
}

__device__ __forceinline__ uint32_t smem_u32(const void* p) {
    uint32_t a;
    asm("{ .reg .u64 t; cvta.to.shared.u64 t, %1; cvt.u32.u64 %0, t; }" : "=r"(a) : "l"(p));
    return a;
}

// ---------------- zero (S1 + deg) ----------------
__global__ void k_zero() {
    int t = blockIdx.x * blockDim.x + threadIdx.x;
    if (t < NN * 4) ((float4*)g_S1)[t] = make_float4(0.f, 0.f, 0.f, 0.f);
    if (t < NN) g_deg[t] = 0;
}

// ---------------- weight packing ----------------
__global__ void k_packW(const float* __restrict__ W1, const float* __restrict__ root1) {
    int idx = blockIdx.x * blockDim.x + threadIdx.x;
    if (idx >= 48 * FIN) return;
    int n = idx >> 10, k = idx & 1023;
    float v;
    if (n < 16)      v = W1[k * 16 + n];
    else if (n < 32) v = W1[FIN * 16 + k * 16 + (n - 16)];
    else             v = root1[k * 16 + (n - 32)];
    __nv_bfloat16 h = __float2bfloat16(v);
    __nv_bfloat16 l = __float2bfloat16(v - __bfloat162float(h));
    g_Wbhi[idx] = h;
    g_Wblo[idx] = l;
}

__global__ void k_pack2(const float* __restrict__ W2, const float* __restrict__ root2) {
    int idx = blockIdx.x * blockDim.x + threadIdx.x;
    if (idx >= 48 * NCLS) return;
    int r = idx / NCLS, c = idx % NCLS;
    float v;
    if (r < 16)      v = W2[r * NCLS + c];
    else if (r < 32) v = W2[16 * NCLS + (r - 16) * NCLS + c];
    else             v = root2[(r - 32) * NCLS + c];
    g_W2cat[idx] = v;
}

// ---------------- GEMM1: A direct-from-gmem fragments, B in SMEM ----------------
#define BST 72   // B smem row stride (bf16 elems)

#define MMA_BF16(d, a0, a1, a2, a3, b0, b1) \
    asm volatile("mma.sync.aligned.m16n8k16.row.col.f32.bf16.bf16.f32 " \
        "{%0,%1,%2,%3}, {%4,%5,%6,%7}, {%8,%9}, {%0,%1,%2,%3};" \
        : "+f"((d)[0]), "+f"((d)[1]), "+f"((d)[2]), "+f"((d)[3]) \
        : "r"(a0), "r"(a1), "r"(a2), "r"(a3), "r"(b0), "r"(b1))

#define LDSM_X4(r0, r1, r2, r3, addr) \
    asm volatile("ldmatrix.sync.aligned.m8n8.x4.shared.b16 {%0,%1,%2,%3}, [%4];" \
        : "=r"(r0), "=r"(r1), "=r"(r2), "=r"(r3) : "r"(addr))

__device__ __forceinline__ uint32_t split_hi(float a, float b, uint32_t& lo) {
    __nv_bfloat162 h = __floats2bfloat162_rn(a, b);
    float ra = a - __low2float(h);
    float rb = b - __high2float(h);
    __nv_bfloat162 L = __floats2bfloat162_rn(ra, rb);
    lo = *(uint32_t*)&L;
    return *(uint32_t*)&h;
}

__device__ __forceinline__ void storeC(long row, int j, float v) {
    if (row >= NN) return;
    if (j < 16)      g_Y[row * 32 + 2 * j] = v;
    else if (j < 32) g_Y[row * 32 + 2 * (j - 16) + 1] = v;
    else             g_R[row * 16 + (j - 32)] = v;
}

__global__ __launch_bounds__(256, 3) void k_gemm1_mma(const float* __restrict__ x) {
    __shared__ __align__(16) __nv_bfloat16 Bs[2][48 * BST];  // [hi|lo]
    int tid = threadIdx.x, w = tid >> 5, l = tid & 31;
    int lq = l >> 2, lr = l & 3;
    long mBase = (long)blockIdx.x * 128;

    long rA = mBase + w * 16 + lq;
    long rA0 = rA < NN ? rA : NN - 1;
    long rA1 = (rA + 8) < NN ? (rA + 8) : NN - 1;
    const float* xr0 = x + rA0 * FIN + 2 * lr;
    const float* xr1 = x + rA1 * FIN + 2 * lr;

    uint32_t bs_hi = smem_u32(&Bs[0][0]);
    uint32_t bs_lo = smem_u32(&Bs[1][0]);
    int n_off = (l & 7) + ((l & 16) ? 8 : 0);
    int kB_off = (l & 8) ? 8 : 0;
    uint32_t bo0 = ((0 * 16 + n_off) * BST + kB_off) * 2;
    uint32_t bo1 = ((1 * 16 + n_off) * BST + kB_off) * 2;
    uint32_t bo2 = ((2 * 16 + n_off) * BST + kB_off) * 2;

    float acc[6][4];
#pragma unroll
    for (int t = 0; t < 6; t++)
#pragma unroll
        for (int i = 0; i < 4; i++) acc[t][i] = 0.f;

    for (int kb = 0; kb < 16; kb++) {
        int k0 = kb * 64;
        __syncthreads();
#pragma unroll
        for (int i = tid; i < 384; i += 256) {
            int n = i >> 3, c8 = (i & 7) * 8;
            uint4 vh = *(const uint4*)(g_Wbhi + n * FIN + k0 + c8);
            uint4 vl = *(const uint4*)(g_Wblo + n * FIN + k0 + c8);
            *(uint4*)&Bs[0][n * BST + c8] = vh;
            *(uint4*)&Bs[1][n * BST + c8] = vl;
        }
        __syncthreads();
#pragma unroll
        for (int ks = 0; ks < 4; ks++) {
            int kc = k0 + ks * 16;
            float2 v00 = *(const float2*)(xr0 + kc);
            float2 v10 = *(const float2*)(xr1 + kc);
            float2 v01 = *(const float2*)(xr0 + kc + 8);
            float2 v11 = *(const float2*)(xr1 + kc + 8);
            uint32_t al0, al1, al2, al3;
            uint32_t ah0 = split_hi(v00.x, v00.y, al0);
            uint32_t ah1 = split_hi(v10.x, v10.y, al1);
            uint32_t ah2 = split_hi(v01.x, v01.y, al2);
            uint32_t ah3 = split_hi(v11.x, v11.y, al3);
            uint32_t ko = ks * 32;
            uint32_t bofs[3] = {bo0, bo1, bo2};
#pragma unroll
            for (int tp = 0; tp < 3; tp++) {
                uint32_t bh0, bh1, bh2, bh3, bl0, bl1, bl2, bl3;
                LDSM_X4(bh0, bh1, bh2, bh3, bs_hi + bofs[tp] + ko);
                LDSM_X4(bl0, bl1, bl2, bl3, bs_lo + bofs[tp] + ko);
                MMA_BF16(acc[2 * tp],     ah0, ah1, ah2, ah3, bh0, bh1);
                MMA_BF16(acc[2 * tp],     ah0, ah1, ah2, ah3, bl0, bl1);
                MMA_BF16(acc[2 * tp],     al0, al1, al2, al3, bh0, bh1);
                MMA_BF16(acc[2 * tp + 1], ah0, ah1, ah2, ah3, bh2, bh3);
                MMA_BF16(acc[2 * tp + 1], ah0, ah1, ah2, ah3, bl2, bl3);
                MMA_BF16(acc[2 * tp + 1], al0, al1, al2, al3, bh2, bh3);
            }
        }
    }
    long r0 = mBase + w * 16 + lq;
#pragma unroll
    for (int t = 0; t < 6; t++) {
        int j = t * 8 + lr * 2;
        storeC(r0,     j,     acc[t][0]);
        storeC(r0,     j + 1, acc[t][1]);
        storeC(r0 + 8, j,     acc[t][2]);
        storeC(r0 + 8, j + 1, acc[t][3]);
    }
}

// ---------------- layer-1 edge aggregation: 4 threads/edge, float4 atomics ----------------
__global__ __launch_bounds__(256) void k_edge1(const int* __restrict__ ei,
                                               const float* __restrict__ pa) {
    int t = blockIdx.x * 256 + threadIdx.x;
    int e = t >> 2;
    if (e >= NE) return;
    int c4 = t & 3;
    int src = clampN(ei[e]);
    int dst = clampN(ei[NE + e]);
    float p = pa[e];
    const float4* yp = (const float4*)(g_Y + src * 32 + 8 * c4);
    float4 ya = yp[0];
    float4 yb = yp[1];
    float4 m;
    m.x = fmaf(p, ya.y - ya.x, ya.x);
    m.y = fmaf(p, ya.w - ya.z, ya.z);
    m.z = fmaf(p, yb.y - yb.x, yb.x);
    m.w = fmaf(p, yb.w - yb.z, yb.z);
    atomicAdd((float4*)(g_S1 + dst * 16 + 4 * c4), m);
    if (c4 == 0) atomicAdd(&g_deg[dst], 1);
}

// ---------------- node update: x1 = elu(S1/deg + R + b1); zero AB ----------------
__global__ __launch_bounds__(256) void k_node1(const float* __restrict__ b1,
                                               float* __restrict__ x1out, int writeOut) {
    int t = blockIdx.x * 256 + threadIdx.x;
    int node = t >> 4;
    if (node >= NN) return;
    int c = t & 15;
    int deg = g_deg[node];
    float inv = 1.f / (float)(deg > 0 ? deg : 1);
    float v = fmaf(g_S1[node * 16 + c], inv, g_R[node * 16 + c] + b1[c]);
    v = (v > 0.f) ? v : expm1f(v);
    g_x1[node * 16 + c] = v;
    if (writeOut) x1out[node * 16 + c] = v;
    g_AB[node * 32 + 2 * c] = 0.f;
    g_AB[node * 32 + 2 * c + 1] = 0.f;
}

// ---------------- layer-2 edge aggregation: 4 threads/edge, float4 atomics ----------------
// g_AB layout per node: [A_0,B_0, A_1,B_1, ..., A_15,B_15]
__global__ __launch_bounds__(256) void k_edge2(const int* __restrict__ ei,
                                               const float* __restrict__ pa) {
    int t = blockIdx.x * 256 + threadIdx.x;
    int e = t >> 2;
    if (e >= NE) return;
    int c4 = t & 3;
    int src = clampN(ei[e]);
    int dst = clampN(ei[NE + e]);
    float p = pa[e];
    float q = 1.f - p;
    float4 xv = *(const float4*)(g_x1 + src * 16 + 4 * c4);
    float4 ab0 = make_float4(q * xv.x, p * xv.x, q * xv.y, p * xv.y);
    float4 ab1 = make_float4(q * xv.z, p * xv.z, q * xv.w, p * xv.w);
    atomicAdd((float4*)(g_AB + dst * 32 + 8 * c4),     ab0);
    atomicAdd((float4*)(g_AB + dst * 32 + 8 * c4 + 4), ab1);
}

// ---------------- GEMM2 + bias + log_softmax (thread per node) ----------------
__global__ __launch_bounds__(256) void k_out(const float* __restrict__ b2,
                                             float* __restrict__ out) {
    __shared__ float Ws[48 * NCLS];
    for (int i = threadIdx.x; i < 48 * NCLS; i += 256) Ws[i] = g_W2cat[i];
    __syncthreads();
    int node = blockIdx.x * 256 + threadIdx.x;
    if (node >= NN) return;

    int deg = g_deg[node];
    float inv = 1.f / (float)(deg > 0 ? deg : 1);

    float acc[NCLS];
#pragma unroll
    for (int cx = 0; cx < NCLS; cx++) acc[cx] = b2[cx];

    const float* ab = g_AB + node * 32;
#pragma unroll 4
    for (int r = 0; r < 16; r++) {
        float a = ab[2 * r] * inv;
        float b = ab[2 * r + 1] * inv;
        const float* wa = &Ws[r * NCLS];
        const float* wb = &Ws[(16 + r) * NCLS];
#pragma unroll
        for (int cx = 0; cx < NCLS; cx++)
            acc[cx] = fmaf(a, wa[cx], fmaf(b, wb[cx], acc[cx]));
    }
    const float* xx = g_x1 + node * 16;
#pragma unroll 4
    for (int r = 0; r < 16; r++) {
        float vv = xx[r];
        const float* wr = &Ws[(32 + r) * NCLS];
#pragma unroll
        for (int cx = 0; cx < NCLS; cx++) acc[cx] = fmaf(vv, wr[cx], acc[cx]);
    }

    float m = acc[0];
#pragma unroll
    for (int cx = 1; cx < NCLS; cx++) m = fmaxf(m, acc[cx]);
    float ssum = 0.f;
#pragma unroll
    for (int cx = 0; cx < NCLS; cx++) ssum += expf(acc[cx] - m);
    float l = m + logf(ssum);
#pragma unroll
    for (int cx = 0; cx < NCLS; cx++) out[node * NCLS + cx] = acc[cx] - l;
}

// ---------------- launch ----------------
extern "C" void kernel_launch(void* const* d_in, const int* in_sizes, int n_in,
                              void* d_out, int out_size) {
    const float* x     = (const float*)d_in[0];
    const int*   ei    = (const int*)d_in[1];     // int32 (jax x64 disabled)
    const float* pa    = (const float*)d_in[2];
    const float* W1    = (const float*)d_in[3];
    const float* root1 = (const float*)d_in[4];
    const float* b1    = (const float*)d_in[5];
    const float* W2    = (const float*)d_in[6];
    const float* root2 = (const float*)d_in[7];
    const float* b2    = (const float*)d_in[8];
    float* out = (float*)d_out;

    int writeOut = (out_size >= NN * (NCLS + HID)) ? 1 : 0;
    float* x1out = out + (long)NN * NCLS;

    // order: k_edge1 is the 4th launch (profiled slot)
    k_packW<<<(48 * FIN + 255) / 256, 256>>>(W1, root1);
    k_zero<<<(NN * 4 + 255) / 256, 256>>>();
    k_gemm1_mma<<<(NN + 127) / 128, 256>>>(x);
    k_edge1<<<(NE * 4) / 256, 256>>>(ei, pa);
    k_node1<<<(NN * 16 + 255) / 256, 256>>>(b1, x1out, writeOut);
    k_edge2<<<(NE * 4) / 256, 256>>>(ei, pa);
    k_pack2<<<(48 * NCLS + 255) / 256, 256>>>(W2, root2);
    k_out<<<(NN + 255) / 256, 256>>>(b2, out);
}